// round 2
// baseline (speedup 1.0000x reference)
#include <cuda_runtime.h>

#define NN 50000
#define NE 800000
#define DIM 128
#define NCLS 10
#define NG 64

// ---- scratch (static device globals; no allocation allowed) ----
__device__ float g_agg[NN * DIM];     // aggregated messages, then input to GEMM
__device__ float g_h2[NN * DIM];      // relu(agg*in_norm @ W + b)
__device__ float g_outdeg[NN];
__device__ float g_indeg[NN];
__device__ int   g_start[NG + 1];     // per-graph node ranges (graph_ids sorted)
__device__ int   g_is64;              // index dtype flag

// ---------------- index dtype detection ----------------
// jax without x64 demotes int64->int32. Values < 50000, so if the buffer is
// int64 every odd 32-bit word is 0. 64 samples => false positive ~(2e-5)^64.
__global__ void detect_kernel(const void* src) {
    const int* p = (const int*)src;
    int is64 = 1;
    for (int i = 0; i < 64; i++)
        if (p[2 * i + 1] != 0) { is64 = 0; break; }
    g_is64 = is64;
}

__device__ __forceinline__ int idx_at(const void* buf, int i, int is64) {
    return is64 ? (int)((const long long*)buf)[i] : ((const int*)buf)[i];
}

// ---------------- zero scratch ----------------
__global__ void zero_kernel() {
    int i = blockIdx.x * blockDim.x + threadIdx.x;
    int stride = gridDim.x * blockDim.x;
    for (int j = i; j < NN * DIM; j += stride) g_agg[j] = 0.f;
    for (int j = i; j < NN; j += stride) { g_outdeg[j] = 0.f; g_indeg[j] = 0.f; }
}

// ---------------- degrees ----------------
__global__ void degree_kernel(const void* src, const void* dst) {
    int e = blockIdx.x * blockDim.x + threadIdx.x;
    if (e >= NE) return;
    int is64 = g_is64;
    int s = idx_at(src, e, is64);
    int d = idx_at(dst, e, is64);
    atomicAdd(&g_outdeg[s], 1.f);
    atomicAdd(&g_indeg[d], 1.f);
}

// ---------------- gather-scatter: agg[dst] += features[src]*out_norm[src] ----
// One warp per edge: 32 lanes x float4 = full 128-float row.
__global__ void scatter_kernel(const float* __restrict__ feat,
                               const void* src, const void* dst) {
    long long gid = (long long)blockIdx.x * blockDim.x + threadIdx.x;
    int e = (int)(gid >> 5);
    if (e >= NE) return;
    int lane = (int)(gid & 31);
    int is64 = g_is64;
    int s = idx_at(src, e, is64);
    int d = idx_at(dst, e, is64);
    float on = rsqrtf(fmaxf(g_outdeg[s], 1.f));
    float4 v = ((const float4*)feat)[s * 32 + lane];
    v.x *= on; v.y *= on; v.z *= on; v.w *= on;
    float* addr = &g_agg[d * DIM + lane * 4];
    asm volatile("red.global.add.v4.f32 [%0], {%1,%2,%3,%4};"
                 :: "l"(addr), "f"(v.x), "f"(v.y), "f"(v.z), "f"(v.w)
                 : "memory");
}

// ---------------- fused in_norm * agg @ W + b -> relu -> h2 ----------------
// BM=128, BN=128(=full OUT_DIM), BK=16, 256 threads, 8x8 micro-tiles.
#define BM 128
#define BN 128
#define BK 16
#define TM 8
#define TN 8

__global__ __launch_bounds__(256, 2)
void gemm_relu_kernel(const float* __restrict__ W, const float* __restrict__ b) {
    __shared__ float As[BK][BM];
    __shared__ float Bs[BK][BN];
    __shared__ float innorm_s[BM];

    int tid = threadIdx.x;
    int m0 = blockIdx.x * BM;

    if (tid < BM) {
        int r = m0 + tid;
        innorm_s[tid] = (r < NN) ? rsqrtf(fmaxf(g_indeg[r], 1.f)) : 0.f;
    }
    __syncthreads();

    float acc[TM][TN] = {};
    int tr = tid >> 4;   // 0..15
    int tc = tid & 15;   // 0..15

    for (int k0 = 0; k0 < DIM; k0 += BK) {
        #pragma unroll
        for (int i = 0; i < 8; i++) {
            int idx = tid + i * 256;
            int r = idx >> 4, c = idx & 15;
            int grow = m0 + r;
            As[c][r] = (grow < NN) ? g_agg[grow * DIM + k0 + c] * innorm_s[r] : 0.f;
        }
        #pragma unroll
        for (int i = 0; i < 8; i++) {
            int idx = tid + i * 256;
            int r = idx >> 7, c = idx & 127;
            Bs[r][c] = W[(k0 + r) * DIM + c];
        }
        __syncthreads();

        #pragma unroll
        for (int k = 0; k < BK; k++) {
            float ra[TM], rb[TN];
            #pragma unroll
            for (int i = 0; i < TM; i++) ra[i] = As[k][tr * TM + i];
            #pragma unroll
            for (int j = 0; j < TN; j++) rb[j] = Bs[k][tc * TN + j];
            #pragma unroll
            for (int i = 0; i < TM; i++)
                #pragma unroll
                for (int j = 0; j < TN; j++)
                    acc[i][j] += ra[i] * rb[j];
        }
        __syncthreads();
    }

    #pragma unroll
    for (int i = 0; i < TM; i++) {
        int grow = m0 + tr * TM + i;
        if (grow < NN) {
            #pragma unroll
            for (int j = 0; j < TN; j++) {
                int col = tc * TN + j;
                float v = acc[i][j] + b[col];
                g_h2[grow * DIM + col] = fmaxf(v, 0.f);
            }
        }
    }
}

// ---------------- graph boundaries (graph_ids sorted ascending) -------------
__global__ void bounds_kernel(const void* gids) {
    int i = blockIdx.x * blockDim.x + threadIdx.x;
    if (i >= NN) return;
    int is64 = g_is64;
    int g = idx_at(gids, i, is64);
    int gp = (i > 0) ? idx_at(gids, i - 1, is64) : -1;
    for (int gg = gp + 1; gg <= g; gg++) g_start[gg] = i;
    if (i == NN - 1)
        for (int gg = g + 1; gg <= NG; gg++) g_start[gg] = NN;
}

// ---------------- segment-mean pool + head GEMM -----------------------------
__global__ void pool_head_kernel(const float* __restrict__ Wh,
                                 const float* __restrict__ bh,
                                 float* __restrict__ out) {
    __shared__ float pooled[DIM];
    int g = blockIdx.x;
    int c = threadIdx.x;  // 128 threads, one per column
    int s = g_start[g], e = g_start[g + 1];
    float sum = 0.f;
    for (int r = s; r < e; r++) sum += g_h2[r * DIM + c];
    float cnt = fmaxf((float)(e - s), 1.f);
    pooled[c] = sum / cnt;
    __syncthreads();
    if (c < NCLS) {
        float acc = bh[c];
        #pragma unroll 4
        for (int d = 0; d < DIM; d++) acc += pooled[d] * Wh[d * NCLS + c];
        out[g * NCLS + c] = acc;
    }
}

// ---------------- launch ----------------
extern "C" void kernel_launch(void* const* d_in, const int* in_sizes, int n_in,
                              void* d_out, int out_size) {
    const float* feat = (const float*)d_in[0];
    const void*  src  = d_in[1];
    const void*  dst  = d_in[2];
    const void*  gids = d_in[3];
    const float* W    = (const float*)d_in[4];
    const float* b    = (const float*)d_in[5];
    const float* Wh   = (const float*)d_in[6];
    const float* bh   = (const float*)d_in[7];
    float* out = (float*)d_out;

    detect_kernel<<<1, 1>>>(src);
    zero_kernel<<<512, 256>>>();
    bounds_kernel<<<(NN + 255) / 256, 256>>>(gids);
    degree_kernel<<<(NE + 255) / 256, 256>>>(src, dst);
    {
        long long total = (long long)NE * 32;
        int blocks = (int)((total + 255) / 256);
        scatter_kernel<<<blocks, 256>>>(feat, src, dst);
    }
    gemm_relu_kernel<<<(NN + BM - 1) / BM, 256>>>(W, b);
    pool_head_kernel<<<NG, DIM>>>(Wh, bh, out);
}

// round 4
// speedup vs baseline: 1.1204x; 1.1204x over previous
#include <cuda_runtime.h>
#include <cuda_bf16.h>
#include <mma.h>
#include <cstdint>

using namespace nvcuda;

#define NN 50000
#define NE 800000
#define DIM 128
#define NCLS 10
#define NG 64
#define NT ((NN + 127) / 128)   // 391 M-tiles

// ---------------- static device scratch ----------------
__device__ __align__(16) float g_Aagg[NT * 128 * DIM]; // normalized agg (GEMM A), fp32
__device__ __align__(16) float g_h2[NN * DIM];         // relu(A@W + b)
__device__ float g_outnorm[NN];
__device__ int   g_outdeg_i[NN];
__device__ int   g_indeg_i[NN];
__device__ int   g_rowptr[NN + 1];
__device__ int   g_cursor[NN];
__device__ int   g_esrc[NE];
__device__ int   g_start[NG + 1];
__device__ int   g_is64;

// ---------------- helpers ----------------
__device__ __forceinline__ int idx_at(const void* buf, int i, int is64) {
    return is64 ? (int)((const long long*)buf)[i] : ((const int*)buf)[i];
}

// ---------------- index dtype detection (1 warp) ----------------
__global__ void detect_kernel(const void* src) {
    const int* p = (const int*)src;
    int t = threadIdx.x;
    int z = (p[2 * t + 1] == 0);
    unsigned m = __ballot_sync(0xffffffffu, z);
    if (t == 0) g_is64 = (m == 0xffffffffu);
}

// ---------------- zero degree counters + A tail rows ----------------
__global__ void zero_kernel() {
    int i = blockIdx.x * blockDim.x + threadIdx.x;
    if (i < NN) { g_outdeg_i[i] = 0; g_indeg_i[i] = 0; }
    const int TAIL = NT * 128 * DIM - NN * DIM;  // 6144
    if (i < TAIL) g_Aagg[NN * DIM + i] = 0.f;
}

// ---------------- degrees (int atomics) ----------------
__global__ void degree_kernel(const void* src, const void* dst) {
    int e = blockIdx.x * blockDim.x + threadIdx.x;
    if (e >= NE) return;
    int is64 = g_is64;
    atomicAdd(&g_outdeg_i[idx_at(src, e, is64)], 1);
    atomicAdd(&g_indeg_i[idx_at(dst, e, is64)], 1);
}

// ---------------- out-degree norms ----------------
__global__ void norms_kernel() {
    int i = blockIdx.x * blockDim.x + threadIdx.x;
    if (i < NN) g_outnorm[i] = rsqrtf(fmaxf((float)g_outdeg_i[i], 1.f));
}

// ---------------- prefix sum of in-degrees -> rowptr & cursor ----------------
__global__ void scan_kernel() {
    __shared__ int sums[1024];
    int t = threadIdx.x;
    const int CH = (NN + 1023) / 1024;
    int beg = t * CH, end = min(beg + CH, NN);
    int s = 0;
    for (int i = beg; i < end; i++) s += g_indeg_i[i];
    sums[t] = s;
    __syncthreads();
    for (int off = 1; off < 1024; off <<= 1) {
        int v = (t >= off) ? sums[t - off] : 0;
        __syncthreads();
        sums[t] += v;
        __syncthreads();
    }
    int run = (t > 0) ? sums[t - 1] : 0;
    for (int i = beg; i < end; i++) {
        g_rowptr[i] = run; g_cursor[i] = run;
        run += g_indeg_i[i];
    }
    if (t == 0) g_rowptr[NN] = NE;
}

// ---------------- fill dst-sorted edge list ----------------
__global__ void fill_kernel(const void* src, const void* dst) {
    int e = blockIdx.x * blockDim.x + threadIdx.x;
    if (e >= NE) return;
    int is64 = g_is64;
    int s = idx_at(src, e, is64);
    int d = idx_at(dst, e, is64);
    int pos = atomicAdd(&g_cursor[d], 1);
    g_esrc[pos] = s;
}

// ---------------- gather: one warp per dst node ----------------
// A[d] = in_norm(d) * sum_{e in CSR(d)} out_norm(src) * feat[src]
__global__ void gather_kernel(const float* __restrict__ feat) {
    int w = (blockIdx.x * blockDim.x + threadIdx.x) >> 5;
    if (w >= NN) return;
    int lane = threadIdx.x & 31;
    int beg = g_rowptr[w], end = g_rowptr[w + 1];

    const float4* f4 = (const float4*)feat;
    float4 acc = make_float4(0.f, 0.f, 0.f, 0.f);

    int e = beg;
    int s_next = (e < end) ? g_esrc[e] : 0;
    while (e < end) {
        int s = s_next;
        ++e;
        s_next = (e < end) ? g_esrc[e] : 0;
        float on = g_outnorm[s];
        float4 v = f4[s * 32 + lane];
        acc.x += v.x * on; acc.y += v.y * on;
        acc.z += v.z * on; acc.w += v.w * on;
    }
    float inn = rsqrtf(fmaxf((float)(end - beg), 1.f));
    acc.x *= inn; acc.y *= inn; acc.z *= inn; acc.w *= inn;

    ((float4*)g_Aagg)[w * 32 + lane] = acc;
}

// ---------------- WMMA tf32 GEMM: h2 = relu(A @ W + b) ----------------
// 128x128 tile, full K=128 in smem. 8 warps, warp-tile 32x64 (2x4 wmma frags).
#define SPAD 132                       // fp32 row stride in smem (132 = 33 float4)
#define SMEM_GEMM (512 + 2 * 128 * SPAD * 4)   // bias + As + Bs = 135680 B

__global__ __launch_bounds__(256)
void gemm_tc_kernel(const float* __restrict__ W, const float* __restrict__ bias) {
    extern __shared__ unsigned char smraw[];
    float* sBias = (float*)smraw;                  // 128 floats
    float* As = (float*)(smraw + 512);             // 128 x 132
    float* Bs = As + 128 * SPAD;                   // 128 x 132  (W[k][n])
    float* Cs = As;                                // epilogue reuse (exact fit)

    int tid = threadIdx.x;
    int wid = tid >> 5;
    int m0 = blockIdx.x * 128;

    if (tid < 128) sBias[tid] = bias[tid];

    // load A tile + W into padded smem (float4 granularity: 33 per row)
    {
        const float4* pa = (const float4*)(g_Aagg + (size_t)m0 * DIM);
        const float4* pw = (const float4*)W;
        float4* sa = (float4*)As;
        float4* sb = (float4*)Bs;
        #pragma unroll
        for (int i = 0; i < 16; i++) {
            int idx = tid + i * 256;      // 0..4095
            int r = idx >> 5, c = idx & 31;
            sa[r * 33 + c] = pa[idx];
            sb[r * 33 + c] = pw[idx];
        }
    }
    __syncthreads();

    int wm = (wid >> 1) * 32;   // 0,32,64,96
    int wn = (wid & 1) * 64;    // 0,64

    wmma::fragment<wmma::accumulator, 16, 16, 8, float> acc[2][4];
    #pragma unroll
    for (int i = 0; i < 2; i++)
        #pragma unroll
        for (int j = 0; j < 4; j++)
            wmma::fill_fragment(acc[i][j], 0.f);

    #pragma unroll
    for (int k0 = 0; k0 < DIM; k0 += 8) {
        wmma::fragment<wmma::matrix_a, 16, 16, 8, wmma::precision::tf32, wmma::row_major> a[2];
        wmma::fragment<wmma::matrix_b, 16, 16, 8, wmma::precision::tf32, wmma::row_major> b[4];
        #pragma unroll
        for (int i = 0; i < 2; i++) {
            wmma::load_matrix_sync(a[i], &As[(wm + i * 16) * SPAD + k0], SPAD);
            #pragma unroll
            for (int t = 0; t < a[i].num_elements; t++)
                a[i].x[t] = wmma::__float_to_tf32(a[i].x[t]);
        }
        #pragma unroll
        for (int j = 0; j < 4; j++) {
            wmma::load_matrix_sync(b[j], &Bs[k0 * SPAD + wn + j * 16], SPAD);
            #pragma unroll
            for (int t = 0; t < b[j].num_elements; t++)
                b[j].x[t] = wmma::__float_to_tf32(b[j].x[t]);
        }
        #pragma unroll
        for (int i = 0; i < 2; i++)
            #pragma unroll
            for (int j = 0; j < 4; j++)
                wmma::mma_sync(acc[i][j], a[i], b[j], acc[i][j]);
    }
    __syncthreads();   // done reading As/Bs; Cs aliases As

    #pragma unroll
    for (int i = 0; i < 2; i++)
        #pragma unroll
        for (int j = 0; j < 4; j++)
            wmma::store_matrix_sync(&Cs[(wm + i * 16) * SPAD + wn + j * 16],
                                    acc[i][j], SPAD, wmma::mem_row_major);
    __syncthreads();

    // bias + relu + write out
    const float4* c4 = (const float4*)Cs;
    float4* h4 = (float4*)g_h2;
    #pragma unroll
    for (int i = 0; i < 16; i++) {
        int idx = tid + i * 256;
        int r = idx >> 5, c = idx & 31;
        int grow = m0 + r;
        if (grow < NN) {
            float4 v = c4[r * 33 + c];
            float4 o;
            o.x = fmaxf(v.x + sBias[c * 4 + 0], 0.f);
            o.y = fmaxf(v.y + sBias[c * 4 + 1], 0.f);
            o.z = fmaxf(v.z + sBias[c * 4 + 2], 0.f);
            o.w = fmaxf(v.w + sBias[c * 4 + 3], 0.f);
            h4[(size_t)grow * 32 + c] = o;
        }
    }
}

// ---------------- graph boundaries (graph_ids sorted ascending) -------------
__global__ void bounds_kernel(const void* gids) {
    int i = blockIdx.x * blockDim.x + threadIdx.x;
    if (i >= NN) return;
    int is64 = g_is64;
    int g = idx_at(gids, i, is64);
    int gp = (i > 0) ? idx_at(gids, i - 1, is64) : -1;
    for (int gg = gp + 1; gg <= g; gg++) g_start[gg] = i;
    if (i == NN - 1)
        for (int gg = g + 1; gg <= NG; gg++) g_start[gg] = NN;
}

// ---------------- segment-mean pool + head GEMM -----------------------------
// 512 threads: 4 row-groups x 128 cols (MLP=4), then reduce.
__global__ void pool_head_kernel(const float* __restrict__ Wh,
                                 const float* __restrict__ bh,
                                 float* __restrict__ out) {
    __shared__ float part[4][DIM];
    __shared__ float pooled[DIM];
    int g = blockIdx.x;
    int c = threadIdx.x & 127;
    int rg = threadIdx.x >> 7;   // 0..3
    int s = g_start[g], e = g_start[g + 1];
    float sum = 0.f;
    for (int r = s + rg; r < e; r += 4) sum += g_h2[(size_t)r * DIM + c];
    part[rg][c] = sum;
    __syncthreads();
    if (rg == 0) {
        float cnt = fmaxf((float)(e - s), 1.f);
        pooled[c] = (part[0][c] + part[1][c] + part[2][c] + part[3][c]) / cnt;
    }
    __syncthreads();
    if (rg == 0 && c < NCLS) {
        float acc = bh[c];
        #pragma unroll 4
        for (int d = 0; d < DIM; d++) acc += pooled[d] * Wh[d * NCLS + c];
        out[g * NCLS + c] = acc;
    }
}

// ---------------- launch ----------------
extern "C" void kernel_launch(void* const* d_in, const int* in_sizes, int n_in,
                              void* d_out, int out_size) {
    const float* feat = (const float*)d_in[0];
    const void*  src  = d_in[1];
    const void*  dst  = d_in[2];
    const void*  gids = d_in[3];
    const float* W    = (const float*)d_in[4];
    const float* b    = (const float*)d_in[5];
    const float* Wh   = (const float*)d_in[6];
    const float* bh   = (const float*)d_in[7];
    float* out = (float*)d_out;

    cudaFuncSetAttribute(gemm_tc_kernel,
                         cudaFuncAttributeMaxDynamicSharedMemorySize, SMEM_GEMM);

    detect_kernel<<<1, 32>>>(src);
    zero_kernel<<<(NN + 255) / 256, 256>>>();
    degree_kernel<<<(NE + 255) / 256, 256>>>(src, dst);
    norms_kernel<<<(NN + 255) / 256, 256>>>();
    scan_kernel<<<1, 1024>>>();
    fill_kernel<<<(NE + 255) / 256, 256>>>(src, dst);
    gather_kernel<<<(NN * 32 + 255) / 256, 256>>>(feat);
    bounds_kernel<<<(NN + 255) / 256, 256>>>(gids);
    gemm_tc_kernel<<<NT, 256, SMEM_GEMM>>>(W, b);
    pool_head_kernel<<<NG, 512>>>(Wh, bh, out);
}